// round 4
// baseline (speedup 1.0000x reference)
#include <cuda_runtime.h>
#include <cuda_bf16.h>
#include <cstdint>
#include <math.h>

#define TILE_E   128
#define NTHREADS 256
#define HDIM     128
#define STRIDE1  72    // bf16 elems per row, GEMM1 tiles (k-chunk 64)
#define STRIDE2  136   // bf16 elems per row, GEMM2 tiles (k = 128)

// ---------------- global scratch: transposed + hi/lo split weights ----------------
__device__ __nv_bfloat16 g_W1T_h[128 * 512];   // [n][k] from W1[k][n]
__device__ __nv_bfloat16 g_W1T_l[128 * 512];
__device__ __nv_bfloat16 g_W2T_h[64 * 128];    // [n][k] from W2[k][n]
__device__ __nv_bfloat16 g_W2T_l[64 * 128];

__global__ void prep_kernel(const float* __restrict__ W1, const float* __restrict__ W2) {
    int i = blockIdx.x * blockDim.x + threadIdx.x;
    if (i < 128 * 512) {
        int n = i >> 9, k = i & 511;
        float x = W1[k * 128 + n];
        __nv_bfloat16 h = __float2bfloat16(x);
        g_W1T_h[i] = h;
        g_W1T_l[i] = __float2bfloat16(x - __bfloat162float(h));
    }
    if (i < 64 * 128) {
        int n = i >> 7, k = i & 127;
        float x = W2[k * 64 + n];
        __nv_bfloat16 h = __float2bfloat16(x);
        g_W2T_h[i] = h;
        g_W2T_l[i] = __float2bfloat16(x - __bfloat162float(h));
    }
}

// ---------------- helpers ----------------
__device__ __forceinline__ uint32_t smem_u32(const void* p) {
    uint32_t a;
    asm("{ .reg .u64 t; cvta.to.shared.u64 t, %1; cvt.u32.u64 %0, t; }" : "=r"(a) : "l"(p));
    return a;
}
#define STS32(addr, v) \
    asm volatile("st.shared.b32 [%0], %1;" :: "r"(addr), "r"(v) : "memory")
#define STS128(addr, v) \
    asm volatile("st.shared.v4.b32 [%0], {%1,%2,%3,%4};" \
        :: "r"(addr), "r"((v).x), "r"((v).y), "r"((v).z), "r"((v).w) : "memory")
#define LDSM4(r, a) \
    asm volatile("ldmatrix.sync.aligned.m8n8.x4.shared.b16 {%0,%1,%2,%3}, [%4];" \
        : "=r"((r)[0]), "=r"((r)[1]), "=r"((r)[2]), "=r"((r)[3]) : "r"(a))
#define MMA16816(c, a, b0v, b1v) \
    asm volatile("mma.sync.aligned.m16n8k16.row.col.f32.bf16.bf16.f32 " \
        "{%0,%1,%2,%3}, {%4,%5,%6,%7}, {%8,%9}, {%0,%1,%2,%3};" \
        : "+f"((c)[0]), "+f"((c)[1]), "+f"((c)[2]), "+f"((c)[3]) \
        : "r"((a)[0]), "r"((a)[1]), "r"((a)[2]), "r"((a)[3]), "r"(b0v), "r"(b1v))

__device__ __forceinline__ uint32_t split2(float x0, float x1, uint32_t& lo2) {
    __nv_bfloat16 h0 = __float2bfloat16(x0), h1 = __float2bfloat16(x1);
    __nv_bfloat16 l0 = __float2bfloat16(x0 - __bfloat162float(h0));
    __nv_bfloat16 l1 = __float2bfloat16(x1 - __bfloat162float(h1));
    lo2 = (uint32_t)__bfloat16_as_ushort(l0) | ((uint32_t)__bfloat16_as_ushort(l1) << 16);
    return (uint32_t)__bfloat16_as_ushort(h0) | ((uint32_t)__bfloat16_as_ushort(h1) << 16);
}

// dynamic smem byte offsets
#define B1_AH 0
#define B1_AL 18432
#define B1_BH 36864
#define B1_BL 55296
#define BUF1_BYTES 73728          // per double-buffer half (GEMM1)
// GEMM2 region (reuses the same memory after GEMM1)
#define G2_AH 0
#define G2_AL 34816
#define G2_BH 69632
#define G2_BL 87040
#define SMEM_DYN (2 * BUF1_BYTES) // 147456

__global__ __launch_bounds__(NTHREADS, 1)
void link_mma_kernel(const float* __restrict__ z,
                     const void* __restrict__ ei_raw,
                     const float* __restrict__ b1g,
                     const float* __restrict__ b2g,
                     const float* __restrict__ w3g,
                     const float* __restrict__ b3g,
                     float* __restrict__ out,
                     int E, int nNodes)
{
    extern __shared__ char dynraw[];
    __shared__ int   s_src[TILE_E], s_dst[TILE_E];
    __shared__ float s_b1[128], s_b2[64], s_w3[64];
    __shared__ float s_b3;
    __shared__ int   s_is64;
    __shared__ float s_part[TILE_E][2];

    const int tid = threadIdx.x;
    const int wid = tid >> 5;
    const int lid = tid & 31;
    const int e0  = blockIdx.x * TILE_E;
    const uint32_t sb = smem_u32(dynraw);

    // ---- setup ----
    if (tid == 0) {
        const long long* e64 = (const long long*)ei_raw;
        int ok = 1;
        #pragma unroll
        for (int i = 0; i < 8; ++i) {
            long long v = e64[i];
            if (v < 0 || v >= (long long)nNodes) { ok = 0; break; }
        }
        s_is64 = ok;
        s_b3 = b3g[0];
    }
    __syncthreads();
    {
        const int is64 = s_is64;
        int t = tid & (TILE_E - 1);
        int e = e0 + t; if (e >= E) e = 0;
        int v;
        if (tid < TILE_E) {
            v = is64 ? (int)((const long long*)ei_raw)[e] : ((const int*)ei_raw)[e];
            s_src[t] = min(max(v, 0), nNodes - 1);
        } else {
            v = is64 ? (int)((const long long*)ei_raw)[(size_t)E + e]
                     : ((const int*)ei_raw)[(size_t)E + e];
            s_dst[t] = min(max(v, 0), nNodes - 1);
        }
        if (tid < 128) s_b1[tid] = b1g[tid];
        if (tid >= 128 && tid < 192) s_b2[tid - 128] = b2g[tid - 128];
        if (tid >= 192) s_w3[tid - 192] = w3g[tid - 192];
    }
    __syncthreads();

    const int wm = wid >> 1;       // 0..3 : 32-row band
    const int wn = wid & 1;        // 0..1 : 64-col band (GEMM1) / 32-col (GEMM2)

    // ---- builders ----
    auto buildA = [&](int c, uint32_t buf) {
        const int seg = c >> 1;                 // 0 src, 1 dst, 2 prod, 3 absdiff
        const int h0  = (c & 1) * 64;
        const uint32_t ah = buf + B1_AH, al = buf + B1_AL;
        #pragma unroll 4
        for (int i = 0; i < 16; ++i) {
            int m = wid * 16 + i;
            const float* zs = z + (size_t)s_src[m] * HDIM + h0 + 2 * lid;
            const float* zd = z + (size_t)s_dst[m] * HDIM + h0 + 2 * lid;
            float2 v;
            if (seg == 0)      v = *(const float2*)zs;
            else if (seg == 1) v = *(const float2*)zd;
            else {
                float2 a = *(const float2*)zs, d = *(const float2*)zd;
                if (seg == 2) { v.x = a.x * d.x;        v.y = a.y * d.y; }
                else          { v.x = fabsf(a.x - d.x); v.y = fabsf(a.y - d.y); }
            }
            uint32_t lo2, hi2 = split2(v.x, v.y, lo2);
            uint32_t off = (uint32_t)m * (STRIDE1 * 2) + (uint32_t)lid * 4;
            STS32(ah + off, hi2);
            STS32(al + off, lo2);
        }
    };
    auto loadB1 = [&](int c, uint32_t buf) {
        const uint32_t bh = buf + B1_BH, bl = buf + B1_BL;
        const char* srcH = (const char*)g_W1T_h;
        const char* srcL = (const char*)g_W1T_l;
        #pragma unroll
        for (int it = 0; it < 4; ++it) {
            int idx = tid + it * NTHREADS;        // 0..1023
            int n = idx >> 3, q = idx & 7;        // n row, q*8 bf16
            uint32_t goff = (uint32_t)n * 1024u + (uint32_t)c * 128u + (uint32_t)q * 16u;
            uint4 vh = __ldg((const uint4*)(srcH + goff));
            uint4 vl = __ldg((const uint4*)(srcL + goff));
            uint32_t soff = (uint32_t)n * (STRIDE1 * 2) + (uint32_t)q * 16u;
            STS128(bh + soff, vh);
            STS128(bl + soff, vl);
        }
    };

    // ---- GEMM1: acc[2][8][4], 8 k-chunks of 64, double buffered ----
    float acc[2][8][4];
    #pragma unroll
    for (int a = 0; a < 2; ++a)
        #pragma unroll
        for (int b = 0; b < 8; ++b)
            #pragma unroll
            for (int d = 0; d < 4; ++d) acc[a][b][d] = 0.f;

    buildA(0, sb); loadB1(0, sb);
    __syncthreads();

    const uint32_t lrow = (uint32_t)(lid & 15);
    const uint32_t lcol = (uint32_t)(lid >> 4) * 8;

    for (int c = 0; c < 8; ++c) {
        const uint32_t buf = sb + (uint32_t)(c & 1) * BUF1_BYTES;
        if (c < 7) {
            const uint32_t nbuf = sb + (uint32_t)((c + 1) & 1) * BUF1_BYTES;
            buildA(c + 1, nbuf);
            loadB1(c + 1, nbuf);
        }
        const uint32_t aH = buf + B1_AH, aL = buf + B1_AL;
        const uint32_t bH = buf + B1_BH, bL = buf + B1_BL;
        #pragma unroll
        for (int ks = 0; ks < 4; ++ks) {
            const uint32_t k0 = (uint32_t)ks * 16;
            uint32_t ah[2][4], al[2][4], bh[4][4], bl[4][4];
            #pragma unroll
            for (int fm = 0; fm < 2; ++fm) {
                uint32_t ra = ((uint32_t)(wm * 32 + fm * 16) + lrow) * (STRIDE1 * 2)
                            + (k0 + lcol) * 2;
                LDSM4(ah[fm], aH + ra);
                LDSM4(al[fm], aL + ra);
            }
            #pragma unroll
            for (int g = 0; g < 4; ++g) {
                uint32_t rb = ((uint32_t)(wn * 64 + g * 16) + lrow) * (STRIDE1 * 2)
                            + (k0 + lcol) * 2;
                LDSM4(bh[g], bH + rb);
                LDSM4(bl[g], bL + rb);
            }
            #pragma unroll
            for (int fm = 0; fm < 2; ++fm)
                #pragma unroll
                for (int fn = 0; fn < 8; ++fn) {
                    const int g = fn >> 1, sel = fn & 1;
                    MMA16816(acc[fm][fn], ah[fm], bh[g][sel], bh[g][sel + 2]);
                    MMA16816(acc[fm][fn], ah[fm], bl[g][sel], bl[g][sel + 2]);
                    MMA16816(acc[fm][fn], al[fm], bh[g][sel], bh[g][sel + 2]);
                }
        }
        __syncthreads();
    }

    // ---- epilogue 1: relu(+b1), split, store A2 tiles ----
    {
        const uint32_t a2h = sb + G2_AH, a2l = sb + G2_AL;
        #pragma unroll
        for (int fm = 0; fm < 2; ++fm)
            #pragma unroll
            for (int fn = 0; fn < 8; ++fn) {
                const int col  = wn * 64 + fn * 8 + (lid & 3) * 2;
                const int row0 = wm * 32 + fm * 16 + (lid >> 2);
                float x0 = fmaxf(acc[fm][fn][0] + s_b1[col],     0.f);
                float x1 = fmaxf(acc[fm][fn][1] + s_b1[col + 1], 0.f);
                float x2 = fmaxf(acc[fm][fn][2] + s_b1[col],     0.f);
                float x3 = fmaxf(acc[fm][fn][3] + s_b1[col + 1], 0.f);
                uint32_t lo2, hi2;
                uint32_t o0 = (uint32_t)row0 * (STRIDE2 * 2) + (uint32_t)col * 2;
                hi2 = split2(x0, x1, lo2);
                STS32(a2h + o0, hi2); STS32(a2l + o0, lo2);
                uint32_t o1 = o0 + 8u * (STRIDE2 * 2);
                hi2 = split2(x2, x3, lo2);
                STS32(a2h + o1, hi2); STS32(a2l + o1, lo2);
            }
        // W2T tiles: 64 rows x 128 k
        const uint32_t b2h = sb + G2_BH, b2l = sb + G2_BL;
        const char* srcH = (const char*)g_W2T_h;
        const char* srcL = (const char*)g_W2T_l;
        #pragma unroll
        for (int it = 0; it < 4; ++it) {
            int idx = tid + it * NTHREADS;        // 0..1023
            int n = idx >> 4, q = idx & 15;
            uint32_t goff = (uint32_t)n * 256u + (uint32_t)q * 16u;
            uint4 vh = __ldg((const uint4*)(srcH + goff));
            uint4 vl = __ldg((const uint4*)(srcL + goff));
            uint32_t soff = (uint32_t)n * (STRIDE2 * 2) + (uint32_t)q * 16u;
            STS128(b2h + soff, vh);
            STS128(b2l + soff, vl);
        }
    }
    __syncthreads();

    // ---- GEMM2: [128,128] x [64,128]^T -> acc2[2][4][4] ----
    float acc2[2][4][4];
    #pragma unroll
    for (int a = 0; a < 2; ++a)
        #pragma unroll
        for (int b = 0; b < 4; ++b)
            #pragma unroll
            for (int d = 0; d < 4; ++d) acc2[a][b][d] = 0.f;
    {
        const uint32_t a2h = sb + G2_AH, a2l = sb + G2_AL;
        const uint32_t b2h = sb + G2_BH, b2l = sb + G2_BL;
        #pragma unroll
        for (int ks = 0; ks < 8; ++ks) {
            const uint32_t k0 = (uint32_t)ks * 16;
            uint32_t ah[2][4], al[2][4], bh[2][4], bl[2][4];
            #pragma unroll
            for (int fm = 0; fm < 2; ++fm) {
                uint32_t ra = ((uint32_t)(wm * 32 + fm * 16) + lrow) * (STRIDE2 * 2)
                            + (k0 + lcol) * 2;
                LDSM4(ah[fm], a2h + ra);
                LDSM4(al[fm], a2l + ra);
            }
            #pragma unroll
            for (int g = 0; g < 2; ++g) {
                uint32_t rb = ((uint32_t)(wn * 32 + g * 16) + lrow) * (STRIDE2 * 2)
                            + (k0 + lcol) * 2;
                LDSM4(bh[g], b2h + rb);
                LDSM4(bl[g], b2l + rb);
            }
            #pragma unroll
            for (int fm = 0; fm < 2; ++fm)
                #pragma unroll
                for (int fn = 0; fn < 4; ++fn) {
                    const int g = fn >> 1, sel = fn & 1;
                    MMA16816(acc2[fm][fn], ah[fm], bh[g][sel], bh[g][sel + 2]);
                    MMA16816(acc2[fm][fn], ah[fm], bl[g][sel], bl[g][sel + 2]);
                    MMA16816(acc2[fm][fn], al[fm], bh[g][sel], bh[g][sel + 2]);
                }
        }
    }

    // ---- epilogue 2: relu(+b2), dot w3, quad-reduce, cross-warp add ----
    #pragma unroll
    for (int fm = 0; fm < 2; ++fm)
        #pragma unroll
        for (int rh = 0; rh < 2; ++rh) {
            float s = 0.f;
            #pragma unroll
            for (int fn = 0; fn < 4; ++fn) {
                const int col = wn * 32 + fn * 8 + (lid & 3) * 2;
                float h0 = fmaxf(acc2[fm][fn][rh * 2 + 0] + s_b2[col],     0.f);
                float h1 = fmaxf(acc2[fm][fn][rh * 2 + 1] + s_b2[col + 1], 0.f);
                s = fmaf(h0, s_w3[col], fmaf(h1, s_w3[col + 1], s));
            }
            s += __shfl_xor_sync(0xffffffffu, s, 1);
            s += __shfl_xor_sync(0xffffffffu, s, 2);
            if ((lid & 3) == 0)
                s_part[wm * 32 + fm * 16 + rh * 8 + (lid >> 2)][wn] = s;
        }
    __syncthreads();
    if (tid < TILE_E) {
        int e = e0 + tid;
        if (e < E) out[e] = s_part[tid][0] + s_part[tid][1] + s_b3;
    }
}

extern "C" void kernel_launch(void* const* d_in, const int* in_sizes, int n_in,
                              void* d_out, int out_size) {
    const float* z  = (const float*)d_in[0];
    const void*  ei = d_in[1];
    const float* W1 = (const float*)d_in[2];
    const float* b1 = (const float*)d_in[3];
    const float* W2 = (const float*)d_in[4];
    const float* b2 = (const float*)d_in[5];
    const float* W3 = (const float*)d_in[6];
    const float* b3 = (const float*)d_in[7];
    float* out = (float*)d_out;

    const int E      = out_size;
    const int nNodes = in_sizes[0] / HDIM;

    prep_kernel<<<256, 256>>>(W1, W2);

    cudaFuncSetAttribute(link_mma_kernel,
                         cudaFuncAttributeMaxDynamicSharedMemorySize, SMEM_DYN);
    const int grid = (E + TILE_E - 1) / TILE_E;
    link_mma_kernel<<<grid, NTHREADS, SMEM_DYN>>>(z, ei, b1, b2, W3, b3,
                                                  out, E, nNodes);
}

// round 5
// speedup vs baseline: 2.1536x; 2.1536x over previous
#include <cuda_runtime.h>
#include <cuda_bf16.h>
#include <cstdint>
#include <math.h>

#define TILE_E   128
#define NTHREADS 512
#define HDIM     128
#define STRIDE1  72    // bf16/row, GEMM1 tiles (144B = 36 words -> conflict-free ldsm)
#define STRIDE2  136   // bf16/row, GEMM2 tiles (272B = 68 words -> conflict-free ldsm)

// ---------------- global scratch: transposed + hi/lo split weights ----------------
__device__ __nv_bfloat16 g_W1T_h[128 * 512];   // [n][k] from W1[k][n]
__device__ __nv_bfloat16 g_W1T_l[128 * 512];
__device__ __nv_bfloat16 g_W2T_h[64 * 128];    // [n][k] from W2[k][n]
__device__ __nv_bfloat16 g_W2T_l[64 * 128];

__global__ void prep_kernel(const float* __restrict__ W1, const float* __restrict__ W2) {
    int i = blockIdx.x * blockDim.x + threadIdx.x;
    if (i < 128 * 512) {
        int n = i >> 9, k = i & 511;
        float x = W1[k * 128 + n];
        __nv_bfloat16 h = __float2bfloat16(x);
        g_W1T_h[i] = h;
        g_W1T_l[i] = __float2bfloat16(x - __bfloat162float(h));
    }
    if (i < 64 * 128) {
        int n = i >> 7, k = i & 127;
        float x = W2[k * 64 + n];
        __nv_bfloat16 h = __float2bfloat16(x);
        g_W2T_h[i] = h;
        g_W2T_l[i] = __float2bfloat16(x - __bfloat162float(h));
    }
}

// ---------------- helpers ----------------
__device__ __forceinline__ uint32_t smem_u32(const void* p) {
    uint32_t a;
    asm("{ .reg .u64 t; cvta.to.shared.u64 t, %1; cvt.u32.u64 %0, t; }" : "=r"(a) : "l"(p));
    return a;
}
#define STS32(addr, v) \
    asm volatile("st.shared.b32 [%0], %1;" :: "r"(addr), "r"(v) : "memory")
#define STS128(addr, v) \
    asm volatile("st.shared.v4.b32 [%0], {%1,%2,%3,%4};" \
        :: "r"(addr), "r"((v).x), "r"((v).y), "r"((v).z), "r"((v).w) : "memory")
#define CP16(saddr, gaddr) \
    asm volatile("cp.async.cg.shared.global [%0], [%1], 16;" \
        :: "r"(saddr), "l"(gaddr) : "memory")
#define CP_COMMIT() asm volatile("cp.async.commit_group;" ::: "memory")
#define CP_WAIT0()  asm volatile("cp.async.wait_group 0;" ::: "memory")
#define LDSM4(r, a) \
    asm volatile("ldmatrix.sync.aligned.m8n8.x4.shared.b16 {%0,%1,%2,%3}, [%4];" \
        : "=r"((r)[0]), "=r"((r)[1]), "=r"((r)[2]), "=r"((r)[3]) : "r"(a))
#define MMA16816(c, a, b0v, b1v) \
    asm volatile("mma.sync.aligned.m16n8k16.row.col.f32.bf16.bf16.f32 " \
        "{%0,%1,%2,%3}, {%4,%5,%6,%7}, {%8,%9}, {%0,%1,%2,%3};" \
        : "+f"((c)[0]), "+f"((c)[1]), "+f"((c)[2]), "+f"((c)[3]) \
        : "r"((a)[0]), "r"((a)[1]), "r"((a)[2]), "r"((a)[3]), "r"(b0v), "r"(b1v))

__device__ __forceinline__ uint32_t split2(float x0, float x1, uint32_t& lo2) {
    __nv_bfloat16 h0 = __float2bfloat16(x0), h1 = __float2bfloat16(x1);
    __nv_bfloat16 l0 = __float2bfloat16(x0 - __bfloat162float(h0));
    __nv_bfloat16 l1 = __float2bfloat16(x1 - __bfloat162float(h1));
    lo2 = (uint32_t)__bfloat16_as_ushort(l0) | ((uint32_t)__bfloat16_as_ushort(l1) << 16);
    return (uint32_t)__bfloat16_as_ushort(h0) | ((uint32_t)__bfloat16_as_ushort(h1) << 16);
}

// GEMM1 double-buffer layout (per half): A hi | A lo | B hi | B lo
#define B1_AH 0
#define B1_AL 18432
#define B1_BH 36864
#define B1_BL 55296
#define BUF1_BYTES 73728
// GEMM2 region (reuses buffer memory after GEMM1):
#define G2_AH 0          // 128 x 272B = 34816
#define G2_AL 34816
#define G2_BH 98304      // 64 x 272B = 17408  (inside old buf1)
#define G2_BL 115712
#define SMEM_DYN (2 * BUF1_BYTES)   // 147456

__global__ __launch_bounds__(NTHREADS)
void link_mma_kernel(const float* __restrict__ z,
                     const void* __restrict__ ei_raw,
                     const float* __restrict__ b1g,
                     const float* __restrict__ b2g,
                     const float* __restrict__ w3g,
                     const float* __restrict__ b3g,
                     float* __restrict__ out,
                     int E, int nNodes)
{
    extern __shared__ char dynraw[];
    __shared__ int   s_src[TILE_E], s_dst[TILE_E];
    __shared__ float s_b1[128], s_b2[64], s_w3[64];
    __shared__ float s_b3;
    __shared__ int   s_is64;
    __shared__ float s_part[TILE_E][2];

    const int tid = threadIdx.x;
    const int wid = tid >> 5;
    const int lid = tid & 31;
    const int e0  = blockIdx.x * TILE_E;
    const uint32_t sb = smem_u32(dynraw);

    // ---- setup ----
    if (tid == 0) {
        const long long* e64 = (const long long*)ei_raw;
        int ok = 1;
        #pragma unroll
        for (int i = 0; i < 8; ++i) {
            long long v = e64[i];
            if (v < 0 || v >= (long long)nNodes) { ok = 0; break; }
        }
        s_is64 = ok;
        s_b3 = b3g[0];
    }
    __syncthreads();
    {
        const int is64 = s_is64;
        if (tid < 256) {
            int t = tid & (TILE_E - 1);
            int e = e0 + t; if (e >= E) e = 0;
            int v;
            if (tid < TILE_E) {
                v = is64 ? (int)((const long long*)ei_raw)[e] : ((const int*)ei_raw)[e];
                s_src[t] = min(max(v, 0), nNodes - 1);
            } else {
                v = is64 ? (int)((const long long*)ei_raw)[(size_t)E + e]
                         : ((const int*)ei_raw)[(size_t)E + e];
                s_dst[t] = min(max(v, 0), nNodes - 1);
            }
        } else if (tid < 384) {
            s_b1[tid - 256] = b1g[tid - 256];
        } else if (tid < 448) {
            s_b2[tid - 384] = b2g[tid - 384];
        } else {
            s_w3[tid - 448] = w3g[tid - 448];
        }
    }
    __syncthreads();

    const int wm = wid >> 1;       // 0..7 : 16-row band
    const int wn = wid & 1;        // 0..1 : 64-col band (GEMM1) / 32-col (GEMM2)
    const uint32_t lrow = (uint32_t)(lid & 15);
    const uint32_t lcol = (uint32_t)(lid >> 4) * 8;

    // ---- pipeline stage helpers ----
    float2 vs[8], vd[8];
    auto stageA = [&](int c) {
        const int half = (c & 1) * 64;
        #pragma unroll
        for (int i = 0; i < 8; ++i) {
            int m = (wid << 3) + i;
            vs[i] = *(const float2*)(z + (size_t)s_src[m] * HDIM + half + 2 * lid);
            vd[i] = *(const float2*)(z + (size_t)s_dst[m] * HDIM + half + 2 * lid);
        }
    };
    auto stsA = [&](int c, uint32_t buf) {
        const int seg = c >> 1;
        const uint32_t ah = buf + B1_AH, al = buf + B1_AL;
        #pragma unroll
        for (int i = 0; i < 8; ++i) {
            int m = (wid << 3) + i;
            float2 v;
            if (seg == 0)      v = vs[i];
            else if (seg == 1) v = vd[i];
            else if (seg == 2) { v.x = vs[i].x * vd[i].x;        v.y = vs[i].y * vd[i].y; }
            else               { v.x = fabsf(vs[i].x - vd[i].x); v.y = fabsf(vs[i].y - vd[i].y); }
            uint32_t lo2, hi2 = split2(v.x, v.y, lo2);
            uint32_t off = (uint32_t)m * (STRIDE1 * 2) + (uint32_t)lid * 4;
            STS32(ah + off, hi2);
            STS32(al + off, lo2);
        }
    };
    auto cpB1 = [&](int c, uint32_t buf) {
        const char* srcH = (const char*)g_W1T_h;
        const char* srcL = (const char*)g_W1T_l;
        #pragma unroll
        for (int it = 0; it < 2; ++it) {
            int idx = tid + it * NTHREADS;     // 0..1023
            int n = idx >> 3, q = idx & 7;
            uint32_t goff = (uint32_t)n * 1024u + (uint32_t)c * 128u + (uint32_t)q * 16u;
            uint32_t soff = (uint32_t)n * (STRIDE1 * 2) + (uint32_t)q * 16u;
            CP16(buf + B1_BH + soff, srcH + goff);
            CP16(buf + B1_BL + soff, srcL + goff);
        }
    };

    // ---- GEMM1: acc[8][4], 8 k-chunks of 64, register-staged pipeline ----
    float acc[8][4];
    #pragma unroll
    for (int b = 0; b < 8; ++b)
        #pragma unroll
        for (int d = 0; d < 4; ++d) acc[b][d] = 0.f;

    // prologue: fill buffer 0
    stageA(0);
    stsA(0, sb);
    cpB1(0, sb);
    CP_COMMIT();
    CP_WAIT0();
    __syncthreads();

    for (int c = 0; c < 8; ++c) {
        const uint32_t buf  = sb + (uint32_t)(c & 1) * BUF1_BYTES;
        const uint32_t nbuf = sb + (uint32_t)((c + 1) & 1) * BUF1_BYTES;
        if (c < 7) {
            cpB1(c + 1, nbuf);      // async, no registers
            CP_COMMIT();
            stageA(c + 1);          // gathers in flight during MMA below
        }
        // ---- MMA on chunk c ----
        {
            const uint32_t aH = buf + B1_AH, aL = buf + B1_AL;
            const uint32_t bH = buf + B1_BH, bL = buf + B1_BL;
            #pragma unroll
            for (int ks = 0; ks < 4; ++ks) {
                const uint32_t k0 = (uint32_t)ks * 16;
                uint32_t ah[4], al[4], bh[4][4], bl[4][4];
                uint32_t ra = ((uint32_t)(wm * 16) + lrow) * (STRIDE1 * 2) + (k0 + lcol) * 2;
                LDSM4(ah, aH + ra);
                LDSM4(al, aL + ra);
                #pragma unroll
                for (int g = 0; g < 4; ++g) {
                    uint32_t rb = ((uint32_t)(wn * 64 + g * 16) + lrow) * (STRIDE1 * 2)
                                + (k0 + lcol) * 2;
                    LDSM4(bh[g], bH + rb);
                    LDSM4(bl[g], bL + rb);
                }
                #pragma unroll
                for (int fn = 0; fn < 8; ++fn) {
                    const int g = fn >> 1, sel = fn & 1;
                    MMA16816(acc[fn], ah, bh[g][sel], bh[g][sel + 2]);
                    MMA16816(acc[fn], ah, bl[g][sel], bl[g][sel + 2]);
                    MMA16816(acc[fn], al, bh[g][sel], bh[g][sel + 2]);
                }
            }
        }
        if (c < 7) stsA(c + 1, nbuf);
        CP_WAIT0();
        __syncthreads();
    }

    // ---- epilogue 1: relu(+b1), split, store A2 (stride 136); cp.async B2 ----
    {
        const uint32_t a2h = sb + G2_AH, a2l = sb + G2_AL;
        #pragma unroll
        for (int fn = 0; fn < 8; ++fn) {
            const int col  = wn * 64 + fn * 8 + (lid & 3) * 2;
            const int row0 = wm * 16 + (lid >> 2);
            float x0 = fmaxf(acc[fn][0] + s_b1[col],     0.f);
            float x1 = fmaxf(acc[fn][1] + s_b1[col + 1], 0.f);
            float x2 = fmaxf(acc[fn][2] + s_b1[col],     0.f);
            float x3 = fmaxf(acc[fn][3] + s_b1[col + 1], 0.f);
            uint32_t lo2, hi2;
            uint32_t o0 = (uint32_t)row0 * (STRIDE2 * 2) + (uint32_t)col * 2;
            hi2 = split2(x0, x1, lo2);
            STS32(a2h + o0, hi2); STS32(a2l + o0, lo2);
            uint32_t o1 = o0 + 8u * (STRIDE2 * 2);
            hi2 = split2(x2, x3, lo2);
            STS32(a2h + o1, hi2); STS32(a2l + o1, lo2);
        }
        // B2 tiles: 64 n-rows x 128 k
        const char* srcH = (const char*)g_W2T_h;
        const char* srcL = (const char*)g_W2T_l;
        #pragma unroll
        for (int it = 0; it < 2; ++it) {
            int idx = tid + it * NTHREADS;     // 0..1023
            int n = idx >> 4, q = idx & 15;
            uint32_t goff = (uint32_t)n * 256u + (uint32_t)q * 16u;
            uint32_t soff = (uint32_t)n * (STRIDE2 * 2) + (uint32_t)q * 16u;
            CP16(sb + G2_BH + soff, srcH + goff);
            CP16(sb + G2_BL + soff, srcL + goff);
        }
        CP_COMMIT();
        CP_WAIT0();
    }
    __syncthreads();

    // ---- GEMM2: [128,128] x [64,128]^T -> acc2[4][4] ----
    float acc2[4][4];
    #pragma unroll
    for (int b = 0; b < 4; ++b)
        #pragma unroll
        for (int d = 0; d < 4; ++d) acc2[b][d] = 0.f;
    {
        const uint32_t a2h = sb + G2_AH, a2l = sb + G2_AL;
        const uint32_t b2h = sb + G2_BH, b2l = sb + G2_BL;
        #pragma unroll
        for (int ks = 0; ks < 8; ++ks) {
            const uint32_t k0 = (uint32_t)ks * 16;
            uint32_t ah[4], al[4], bh[2][4], bl[2][4];
            uint32_t ra = ((uint32_t)(wm * 16) + lrow) * (STRIDE2 * 2) + (k0 + lcol) * 2;
            LDSM4(ah, a2h + ra);
            LDSM4(al, a2l + ra);
            #pragma unroll
            for (int g = 0; g < 2; ++g) {
                uint32_t rb = ((uint32_t)(wn * 32 + g * 16) + lrow) * (STRIDE2 * 2)
                            + (k0 + lcol) * 2;
                LDSM4(bh[g], b2h + rb);
                LDSM4(bl[g], b2l + rb);
            }
            #pragma unroll
            for (int fn = 0; fn < 4; ++fn) {
                const int g = fn >> 1, sel = fn & 1;
                MMA16816(acc2[fn], ah, bh[g][sel], bh[g][sel + 2]);
                MMA16816(acc2[fn], ah, bl[g][sel], bl[g][sel + 2]);
                MMA16816(acc2[fn], al, bh[g][sel], bh[g][sel + 2]);
            }
        }
    }

    // ---- epilogue 2: relu(+b2), dot w3, quad-reduce, cross-warp add ----
    #pragma unroll
    for (int rh = 0; rh < 2; ++rh) {
        float s = 0.f;
        #pragma unroll
        for (int fn = 0; fn < 4; ++fn) {
            const int col = wn * 32 + fn * 8 + (lid & 3) * 2;
            float h0 = fmaxf(acc2[fn][rh * 2 + 0] + s_b2[col],     0.f);
            float h1 = fmaxf(acc2[fn][rh * 2 + 1] + s_b2[col + 1], 0.f);
            s = fmaf(h0, s_w3[col], fmaf(h1, s_w3[col + 1], s));
        }
        s += __shfl_xor_sync(0xffffffffu, s, 1);
        s += __shfl_xor_sync(0xffffffffu, s, 2);
        if ((lid & 3) == 0)
            s_part[wm * 16 + rh * 8 + (lid >> 2)][wn] = s;
    }
    __syncthreads();
    if (tid < TILE_E) {
        int e = e0 + tid;
        if (e < E) out[e] = s_part[tid][0] + s_part[tid][1] + s_b3;
    }
}

extern "C" void kernel_launch(void* const* d_in, const int* in_sizes, int n_in,
                              void* d_out, int out_size) {
    const float* z  = (const float*)d_in[0];
    const void*  ei = d_in[1];
    const float* W1 = (const float*)d_in[2];
    const float* b1 = (const float*)d_in[3];
    const float* W2 = (const float*)d_in[4];
    const float* b2 = (const float*)d_in[5];
    const float* W3 = (const float*)d_in[6];
    const float* b3 = (const float*)d_in[7];
    float* out = (float*)d_out;

    const int E      = out_size;
    const int nNodes = in_sizes[0] / HDIM;

    prep_kernel<<<256, 256>>>(W1, W2);

    cudaFuncSetAttribute(link_mma_kernel,
                         cudaFuncAttributeMaxDynamicSharedMemorySize, SMEM_DYN);
    const int grid = (E + TILE_E - 1) / TILE_E;
    link_mma_kernel<<<grid, NTHREADS, SMEM_DYN>>>(z, ei, b1, b2, W3, b3,
                                                  out, E, nNodes);
}

// round 6
// speedup vs baseline: 2.1694x; 1.0073x over previous
#include <cuda_runtime.h>
#include <cuda_bf16.h>
#include <cstdint>
#include <math.h>

#define TILE_E   128
#define NTHREADS 512
#define HDIM     128
#define STRIDE1B 144   // bytes/row, GEMM1 tiles (36 words -> conflict-free ldsm)
#define STRIDE2B 272   // bytes/row, GEMM2 tiles (68 words -> conflict-free ldsm)

// ---------------- global scratch: transposed + hi/lo split weights ----------------
__device__ __nv_bfloat16 g_W1T_h[128 * 512];   // [n][k] from W1[k][n]
__device__ __nv_bfloat16 g_W1T_l[128 * 512];
__device__ __nv_bfloat16 g_W2T_h[64 * 128];    // [n][k] from W2[k][n]
__device__ __nv_bfloat16 g_W2T_l[64 * 128];

__global__ void prep_kernel(const float* __restrict__ W1, const float* __restrict__ W2) {
    int i = blockIdx.x * blockDim.x + threadIdx.x;
    if (i < 128 * 512) {
        int n = i >> 9, k = i & 511;
        float x = W1[k * 128 + n];
        __nv_bfloat16 h = __float2bfloat16(x);
        g_W1T_h[i] = h;
        g_W1T_l[i] = __float2bfloat16(x - __bfloat162float(h));
    }
    if (i < 64 * 128) {
        int n = i >> 7, k = i & 127;
        float x = W2[k * 64 + n];
        __nv_bfloat16 h = __float2bfloat16(x);
        g_W2T_h[i] = h;
        g_W2T_l[i] = __float2bfloat16(x - __bfloat162float(h));
    }
}

// ---------------- helpers ----------------
__device__ __forceinline__ uint32_t smem_u32(const void* p) {
    uint32_t a;
    asm("{ .reg .u64 t; cvta.to.shared.u64 t, %1; cvt.u32.u64 %0, t; }" : "=r"(a) : "l"(p));
    return a;
}
#define STS32(addr, v) \
    asm volatile("st.shared.b32 [%0], %1;" :: "r"(addr), "r"(v) : "memory")
#define CP16(saddr, gaddr) \
    asm volatile("cp.async.cg.shared.global [%0], [%1], 16;" \
        :: "r"(saddr), "l"(gaddr) : "memory")
#define CP_COMMIT() asm volatile("cp.async.commit_group;" ::: "memory")
#define CP_WAIT0()  asm volatile("cp.async.wait_group 0;" ::: "memory")
#define LDSM4(r, a) \
    asm volatile("ldmatrix.sync.aligned.m8n8.x4.shared.b16 {%0,%1,%2,%3}, [%4];" \
        : "=r"((r)[0]), "=r"((r)[1]), "=r"((r)[2]), "=r"((r)[3]) : "r"(a))
#define MMA16816(c, a, b0v, b1v) \
    asm volatile("mma.sync.aligned.m16n8k16.row.col.f32.bf16.bf16.f32 " \
        "{%0,%1,%2,%3}, {%4,%5,%6,%7}, {%8,%9}, {%0,%1,%2,%3};" \
        : "+f"((c)[0]), "+f"((c)[1]), "+f"((c)[2]), "+f"((c)[3]) \
        : "r"((a)[0]), "r"((a)[1]), "r"((a)[2]), "r"((a)[3]), "r"(b0v), "r"(b1v))

__device__ __forceinline__ uint32_t split2(float x0, float x1, uint32_t& lo2) {
    __nv_bfloat16 h0 = __float2bfloat16(x0), h1 = __float2bfloat16(x1);
    __nv_bfloat16 l0 = __float2bfloat16(x0 - __bfloat162float(h0));
    __nv_bfloat16 l1 = __float2bfloat16(x1 - __bfloat162float(h1));
    lo2 = (uint32_t)__bfloat16_as_ushort(l0) | ((uint32_t)__bfloat16_as_ushort(l1) << 16);
    return (uint32_t)__bfloat16_as_ushort(h0) | ((uint32_t)__bfloat16_as_ushort(h1) << 16);
}

// GEMM1 double-buffer layout (per half): A hi | A lo | B hi | B lo  (each 128x144B)
#define B1_AH 0
#define B1_AL 18432
#define B1_BH 36864
#define B1_BL 55296
#define BUF1_BYTES 73728
// GEMM2 regions: A reuses buffer0 after GEMM1; B2 has a dedicated region,
// prefetched once at kernel start.
#define G2_AH 0           // 128 x 272B = 34816
#define G2_AL 34816
#define G2_BH 147456      // 64 x 272B = 17408
#define G2_BL 164864
#define SMEM_DYN 182272

__global__ __launch_bounds__(NTHREADS)
void link_mma_kernel(const float* __restrict__ z,
                     const void* __restrict__ ei_raw,
                     const float* __restrict__ b1g,
                     const float* __restrict__ b2g,
                     const float* __restrict__ w3g,
                     const float* __restrict__ b3g,
                     float* __restrict__ out,
                     int E, int nNodes)
{
    extern __shared__ char dynraw[];
    __shared__ int   s_src[TILE_E], s_dst[TILE_E];
    __shared__ float s_b1[128], s_b2[64], s_w3[64];
    __shared__ float s_b3;
    __shared__ int   s_is64;
    __shared__ float s_part[TILE_E][4];

    const int tid = threadIdx.x;
    const int wid = tid >> 5;
    const int lid = tid & 31;
    const int e0  = blockIdx.x * TILE_E;
    const uint32_t sb = smem_u32(dynraw);

    // ---- setup ----
    if (tid == 0) {
        const long long* e64 = (const long long*)ei_raw;
        int ok = 1;
        #pragma unroll
        for (int i = 0; i < 8; ++i) {
            long long v = e64[i];
            if (v < 0 || v >= (long long)nNodes) { ok = 0; break; }
        }
        s_is64 = ok;
        s_b3 = b3g[0];
    }
    __syncthreads();
    {
        const int is64 = s_is64;
        if (tid < 256) {
            int t = tid & (TILE_E - 1);
            int e = e0 + t; if (e >= E) e = 0;
            int v;
            if (tid < TILE_E) {
                v = is64 ? (int)((const long long*)ei_raw)[e] : ((const int*)ei_raw)[e];
                s_src[t] = min(max(v, 0), nNodes - 1);
            } else {
                v = is64 ? (int)((const long long*)ei_raw)[(size_t)E + e]
                         : ((const int*)ei_raw)[(size_t)E + e];
                s_dst[t] = min(max(v, 0), nNodes - 1);
            }
        } else if (tid < 384) {
            s_b1[tid - 256] = b1g[tid - 256];
        } else if (tid < 448) {
            s_b2[tid - 384] = b2g[tid - 384];
        } else {
            s_w3[tid - 448] = w3g[tid - 448];
        }
    }
    __syncthreads();

    const int wm = wid >> 2;       // 0..3 : 32-row band
    const int wn = wid & 3;        // 0..3 : 32-col band (GEMM1) / 16-col (GEMM2)
    const uint32_t lrow = (uint32_t)(lid & 15);
    const uint32_t lcol = (uint32_t)(lid >> 4) * 8;

    // ---- pipeline stage helpers ----
    float2 vs[8], vd[8];
    auto stageA = [&](int c) {
        const int half = (c & 1) * 64;
        #pragma unroll
        for (int i = 0; i < 8; ++i) {
            int m = (wid << 3) + i;
            vs[i] = *(const float2*)(z + (size_t)s_src[m] * HDIM + half + 2 * lid);
            vd[i] = *(const float2*)(z + (size_t)s_dst[m] * HDIM + half + 2 * lid);
        }
    };
    auto stsA = [&](int c, uint32_t buf) {
        const int seg = c >> 1;
        const uint32_t ah = buf + B1_AH, al = buf + B1_AL;
        #pragma unroll
        for (int i = 0; i < 8; ++i) {
            int m = (wid << 3) + i;
            float2 v;
            if (seg == 0)      v = vs[i];
            else if (seg == 1) v = vd[i];
            else if (seg == 2) { v.x = vs[i].x * vd[i].x;        v.y = vs[i].y * vd[i].y; }
            else               { v.x = fabsf(vs[i].x - vd[i].x); v.y = fabsf(vs[i].y - vd[i].y); }
            uint32_t lo2, hi2 = split2(v.x, v.y, lo2);
            uint32_t off = (uint32_t)m * STRIDE1B + (uint32_t)lid * 4;
            STS32(ah + off, hi2);
            STS32(al + off, lo2);
        }
    };
    auto cpB1 = [&](int c, uint32_t buf) {
        const char* srcH = (const char*)g_W1T_h;
        const char* srcL = (const char*)g_W1T_l;
        #pragma unroll
        for (int it = 0; it < 2; ++it) {
            int idx = tid + it * NTHREADS;     // 0..1023
            int n = idx >> 3, q = idx & 7;
            uint32_t goff = (uint32_t)n * 1024u + (uint32_t)c * 128u + (uint32_t)q * 16u;
            uint32_t soff = (uint32_t)n * STRIDE1B + (uint32_t)q * 16u;
            CP16(buf + B1_BH + soff, srcH + goff);
            CP16(buf + B1_BL + soff, srcL + goff);
        }
    };

    // ---- GEMM1: acc[2][4][4], 8 k-chunks of 64, register-staged pipeline ----
    float acc[2][4][4];
    #pragma unroll
    for (int a = 0; a < 2; ++a)
        #pragma unroll
        for (int b = 0; b < 4; ++b)
            #pragma unroll
            for (int d = 0; d < 4; ++d) acc[a][b][d] = 0.f;

    // prologue: fill buffer 0 + prefetch all of B2 (consumed only after GEMM1)
    stageA(0);
    stsA(0, sb);
    cpB1(0, sb);
    {
        const char* srcH = (const char*)g_W2T_h;
        const char* srcL = (const char*)g_W2T_l;
        #pragma unroll
        for (int it = 0; it < 2; ++it) {
            int idx = tid + it * NTHREADS;     // 0..1023
            int n = idx >> 4, q = idx & 15;
            uint32_t goff = (uint32_t)n * 256u + (uint32_t)q * 16u;
            uint32_t soff = (uint32_t)n * STRIDE2B + (uint32_t)q * 16u;
            CP16(sb + G2_BH + soff, srcH + goff);
            CP16(sb + G2_BL + soff, srcL + goff);
        }
    }
    CP_COMMIT();
    CP_WAIT0();
    __syncthreads();

    for (int c = 0; c < 8; ++c) {
        const uint32_t buf  = sb + (uint32_t)(c & 1) * BUF1_BYTES;
        const uint32_t nbuf = sb + (uint32_t)((c + 1) & 1) * BUF1_BYTES;
        if (c < 7) {
            cpB1(c + 1, nbuf);      // async, no registers
            CP_COMMIT();
            stageA(c + 1);          // gathers in flight during MMA below
        }
        // ---- MMA on chunk c (warp tile 32x32) ----
        {
            const uint32_t rowoff = (wm * 32u + lrow) * STRIDE1B + lcol * 2u;
            const uint32_t noff   = (wn * 32u + lrow) * STRIDE1B + lcol * 2u;
            const uint32_t aH = buf + B1_AH + rowoff;
            const uint32_t aL = buf + B1_AL + rowoff;
            const uint32_t bH = buf + B1_BH + noff;
            const uint32_t bL = buf + B1_BL + noff;
            #pragma unroll
            for (int ks = 0; ks < 4; ++ks) {
                const uint32_t ko = (uint32_t)ks * 32u;
                uint32_t ah[2][4], al[2][4], bh[2][4], bl[2][4];
                LDSM4(ah[0], aH + ko);
                LDSM4(ah[1], aH + ko + 16u * STRIDE1B);
                LDSM4(al[0], aL + ko);
                LDSM4(al[1], aL + ko + 16u * STRIDE1B);
                LDSM4(bh[0], bH + ko);
                LDSM4(bh[1], bH + ko + 16u * STRIDE1B);
                LDSM4(bl[0], bL + ko);
                LDSM4(bl[1], bL + ko + 16u * STRIDE1B);
                #pragma unroll
                for (int fm = 0; fm < 2; ++fm)
                    #pragma unroll
                    for (int fn = 0; fn < 4; ++fn) {
                        const int g = fn >> 1, sel = fn & 1;
                        MMA16816(acc[fm][fn], ah[fm], bh[g][sel], bh[g][sel + 2]);
                        MMA16816(acc[fm][fn], ah[fm], bl[g][sel], bl[g][sel + 2]);
                        MMA16816(acc[fm][fn], al[fm], bh[g][sel], bh[g][sel + 2]);
                    }
            }
        }
        if (c < 7) stsA(c + 1, nbuf);
        CP_WAIT0();
        __syncthreads();
    }

    // ---- epilogue 1: relu(+b1), split, store A2 (stride 272B) ----
    {
        const uint32_t a2h = sb + G2_AH, a2l = sb + G2_AL;
        #pragma unroll
        for (int fm = 0; fm < 2; ++fm)
            #pragma unroll
            for (int fn = 0; fn < 4; ++fn) {
                const int col  = wn * 32 + fn * 8 + (lid & 3) * 2;
                const int row0 = wm * 32 + fm * 16 + (lid >> 2);
                float x0 = fmaxf(acc[fm][fn][0] + s_b1[col],     0.f);
                float x1 = fmaxf(acc[fm][fn][1] + s_b1[col + 1], 0.f);
                float x2 = fmaxf(acc[fm][fn][2] + s_b1[col],     0.f);
                float x3 = fmaxf(acc[fm][fn][3] + s_b1[col + 1], 0.f);
                uint32_t lo2, hi2;
                uint32_t o0 = (uint32_t)row0 * STRIDE2B + (uint32_t)col * 2;
                hi2 = split2(x0, x1, lo2);
                STS32(a2h + o0, hi2); STS32(a2l + o0, lo2);
                uint32_t o1 = o0 + 8u * STRIDE2B;
                hi2 = split2(x2, x3, lo2);
                STS32(a2h + o1, hi2); STS32(a2l + o1, lo2);
            }
    }
    __syncthreads();

    // ---- GEMM2: [128,128] x [64,128]^T -> acc2[2][2][4] (warp tile 32x16) ----
    float acc2[2][2][4];
    #pragma unroll
    for (int a = 0; a < 2; ++a)
        #pragma unroll
        for (int b = 0; b < 2; ++b)
            #pragma unroll
            for (int d = 0; d < 4; ++d) acc2[a][b][d] = 0.f;
    {
        const uint32_t rowoff = (wm * 32u + lrow) * STRIDE2B + lcol * 2u;
        const uint32_t noff   = (wn * 16u + lrow) * STRIDE2B + lcol * 2u;
        const uint32_t a2H = sb + G2_AH + rowoff;
        const uint32_t a2L = sb + G2_AL + rowoff;
        const uint32_t b2H = sb + G2_BH + noff;
        const uint32_t b2L = sb + G2_BL + noff;
        #pragma unroll
        for (int ks = 0; ks < 8; ++ks) {
            const uint32_t ko = (uint32_t)ks * 32u;
            uint32_t ah[2][4], al[2][4], bh[4], bl[4];
            LDSM4(ah[0], a2H + ko);
            LDSM4(ah[1], a2H + ko + 16u * STRIDE2B);
            LDSM4(al[0], a2L + ko);
            LDSM4(al[1], a2L + ko + 16u * STRIDE2B);
            LDSM4(bh, b2H + ko);
            LDSM4(bl, b2L + ko);
            #pragma unroll
            for (int fm = 0; fm < 2; ++fm)
                #pragma unroll
                for (int fn = 0; fn < 2; ++fn) {
                    MMA16816(acc2[fm][fn], ah[fm], bh[fn], bh[fn + 2]);
                    MMA16816(acc2[fm][fn], ah[fm], bl[fn], bl[fn + 2]);
                    MMA16816(acc2[fm][fn], al[fm], bh[fn], bh[fn + 2]);
                }
        }
    }

    // ---- epilogue 2: relu(+b2), dot w3, quad-reduce, cross-band add ----
    #pragma unroll
    for (int fm = 0; fm < 2; ++fm)
        #pragma unroll
        for (int rh = 0; rh < 2; ++rh) {
            float s = 0.f;
            #pragma unroll
            for (int fn = 0; fn < 2; ++fn) {
                const int col = wn * 16 + fn * 8 + (lid & 3) * 2;
                float h0 = fmaxf(acc2[fm][fn][rh * 2 + 0] + s_b2[col],     0.f);
                float h1 = fmaxf(acc2[fm][fn][rh * 2 + 1] + s_b2[col + 1], 0.f);
                s = fmaf(h0, s_w3[col], fmaf(h1, s_w3[col + 1], s));
            }
            s += __shfl_xor_sync(0xffffffffu, s, 1);
            s += __shfl_xor_sync(0xffffffffu, s, 2);
            if ((lid & 3) == 0)
                s_part[wm * 32 + fm * 16 + rh * 8 + (lid >> 2)][wn] = s;
        }
    __syncthreads();
    if (tid < TILE_E) {
        int e = e0 + tid;
        if (e < E)
            out[e] = s_part[tid][0] + s_part[tid][1]
                   + s_part[tid][2] + s_part[tid][3] + s_b3;
    }
}

extern "C" void kernel_launch(void* const* d_in, const int* in_sizes, int n_in,
                              void* d_out, int out_size) {
    const float* z  = (const float*)d_in[0];
    const void*  ei = d_in[1];
    const float* W1 = (const float*)d_in[2];
    const float* b1 = (const float*)d_in[3];
    const float* W2 = (const float*)d_in[4];
    const float* b2 = (const float*)d_in[5];
    const float* W3 = (const float*)d_in[6];
    const float* b3 = (const float*)d_in[7];
    float* out = (float*)d_out;

    const int E      = out_size;
    const int nNodes = in_sizes[0] / HDIM;

    prep_kernel<<<256, 256>>>(W1, W2);

    cudaFuncSetAttribute(link_mma_kernel,
                         cudaFuncAttributeMaxDynamicSharedMemorySize, SMEM_DYN);
    const int grid = (E + TILE_E - 1) / TILE_E;
    link_mma_kernel<<<grid, NTHREADS, SMEM_DYN>>>(z, ei, b1, b2, W3, b3,
                                                  out, E, nNodes);
}